// round 12
// baseline (speedup 1.0000x reference)
#include <cuda_runtime.h>
#include <cuda_fp16.h>
#include <cstdint>

// ============================================================================
// DistNet: out[n] = sigmoid((max(0, ||x||^2 + min_p(||p||^2 - 2 x.p)) + alpha)/beta)
// R12: R7 core, but sharing unit = QUAD (4 warps, m128) instead of pair:
// MTILE=128, each B smem byte amortized over 128 rows -> smem crossbar
// traffic 0.094 -> 0.078 B/MAC. Single fused kernel, quad-private double
// buffers, 128-thread named barriers, fp16 m16n8k16 f16-acc HMMA.
// ============================================================================

static constexpr int NROWS  = 65536;
static constexpr int DIM    = 128;
static constexpr int NPTS   = 2048;
static constexpr int MTILE  = 128;
static constexpr int SUBPTS = 32;             // points per sub-chunk
static constexpr int NSUB   = 1024 / SUBPTS;  // 32 sub-chunks per quad (1024 pts)

#define LOG1000F 6.9077542789816375f

__device__ __align__(16) __half g_pts[NPTS * DIM];  // fp16 points, K-major
__device__ __align__(16) __half g_pn[NPTS];         // ||p||^2 (fp16)

// smem layout (dynamic)
static constexpr int OFF_X     = 0;                    // 128 x 256B = 32768
static constexpr int OFF_B     = 32768;
static constexpr int BUFBYTES  = SUBPTS * 256;         // 8192 per stage buffer
static constexpr int BUFSTRIDE = BUFBYTES + 128;       // + pn (64B) + pad
static constexpr int QUADBYTES = 2 * BUFSTRIDE;        // double buffer
static constexpr int OFF_XN    = OFF_B + 2 * QUADBYTES;   // 66048, 512B
static constexpr int OFF_MIN   = OFF_XN + 512;            // 128 floats
static constexpr int SMEM_BYTES = OFF_MIN + 512 + 128;    // ~67200 -> occ 2

// ---------------------------------------------------------------------------
__device__ __forceinline__ uint32_t smem_u32(const void* p) {
    uint32_t a;
    asm("{ .reg .u64 t; cvta.to.shared.u64 t, %1; cvt.u32.u64 %0, t; }"
        : "=r"(a) : "l"(p));
    return a;
}

__device__ __forceinline__ void cp_async16(uint32_t dst, const void* src) {
    asm volatile("cp.async.cg.shared.global [%0], [%1], 16;"
                 :: "r"(dst), "l"(src) : "memory");
}

#define LDMATRIX_X4(R, ADDR)                                                   \
    asm volatile("ldmatrix.sync.aligned.m8n8.x4.shared.b16 {%0,%1,%2,%3}, [%4];" \
                 : "=r"((R)[0]), "=r"((R)[1]), "=r"((R)[2]), "=r"((R)[3])       \
                 : "r"(ADDR))

#define MMA16816H(C, A, B0, B1)                                                \
    asm volatile("mma.sync.aligned.m16n8k16.row.col.f16.f16.f16.f16 "          \
                 "{%0,%1}, {%2,%3,%4,%5}, {%6,%7}, {%0,%1};"                   \
                 : "+r"((C)[0]), "+r"((C)[1])                                  \
                 : "r"((A)[0]), "r"((A)[1]), "r"((A)[2]), "r"((A)[3]),         \
                   "r"(B0), "r"(B1))

// ---------------------------------------------------------------------------
// Prep: points f32 -> fp16 row-major + ||p||^2 (fp16)
__global__ void distnet_prep(const float* __restrict__ pts) {
    int p = blockIdx.x;
    int t = threadIdx.x;  // 128 = DIM
    float v = pts[p * DIM + t];
    g_pts[p * DIM + t] = __float2half(v);
    float s = v * v;
#pragma unroll
    for (int o = 16; o > 0; o >>= 1) s += __shfl_xor_sync(0xffffffffu, s, o);
    __shared__ float ws[4];
    if ((t & 31) == 0) ws[t >> 5] = s;
    __syncthreads();
    if (t == 0) g_pn[p] = __float2half(ws[0] + ws[1] + ws[2] + ws[3]);
}

// ---------------------------------------------------------------------------
// Quad-scope async copy of one 32-point sub-chunk (8KB B + 64B pn).
// tq = thread index within the 128-thread quad. base = first point index.
__device__ __forceinline__ void issue_sub(uint32_t dst, int base, int sub, int tq) {
    const char* src = (const char*)g_pts + ((size_t)base + sub * SUBPTS) * 256;
#pragma unroll
    for (int u = 0; u < 4; u++) {
        int i = tq + u * 128;            // 0..511 16B units
        int n = i >> 4, c = i & 15;
        cp_async16(dst + n * 256 + ((c ^ (n & 7)) * 16), src + i * 16);
    }
    if (tq < 4)
        cp_async16(dst + BUFBYTES + tq * 16,
                   (const char*)g_pn + ((size_t)base + sub * SUBPTS) * 2 + tq * 16);
    asm volatile("cp.async.commit_group;" ::: "memory");
}

// ---------------------------------------------------------------------------
__global__ void __launch_bounds__(256, 2)
distnet_main(const float* __restrict__ x, const float* __restrict__ beta_raw,
             float* __restrict__ out) {
    extern __shared__ char smem[];
    const uint32_t sb = smem_u32(smem);
    const int tid   = threadIdx.x;
    const int lane  = tid & 31;
    const int wid   = tid >> 5;        // 0..7
    const int mq    = wid & 3;         // m-quarter (32 rows of the 128-row tile)
    const int quad  = wid >> 2;        // 0..1, owns points [1024*quad, +1024)
    const int tq    = tid & 127;       // thread index within quad
    const int row0  = blockIdx.x * MTILE;

    const uint32_t buf0 = sb + OFF_B + quad * QUADBYTES;
    const uint32_t buf1 = buf0 + BUFSTRIDE;
    const int pbase = quad * 1024;

    issue_sub(buf0, pbase, 0, tq);     // prefetch sub-chunk 0

    // ---- X tile: 128 rows x 256B fp16, 4 threads per row + ||x||^2
    {
        int sub = tid & 3;
#pragma unroll
        for (int pass = 0; pass < 2; pass++) {
            int r = (tid >> 2) + pass * 64;   // 0..127
            const float4* src = (const float4*)(x + (size_t)(row0 + r) * DIM);
            float s = 0.f;
#pragma unroll
            for (int j = 0; j < 4; j++) {
                int c = j * 4 + sub;          // 16B fp16 unit
                float4 v0 = src[c * 2], v1 = src[c * 2 + 1];
                s += v0.x * v0.x + v0.y * v0.y + v0.z * v0.z + v0.w * v0.w;
                s += v1.x * v1.x + v1.y * v1.y + v1.z * v1.z + v1.w * v1.w;
                __half2 p0 = __floats2half2_rn(v0.x, v0.y);
                __half2 p1 = __floats2half2_rn(v0.z, v0.w);
                __half2 p2 = __floats2half2_rn(v1.x, v1.y);
                __half2 p3 = __floats2half2_rn(v1.z, v1.w);
                uint4 pk;
                pk.x = *(uint32_t*)&p0; pk.y = *(uint32_t*)&p1;
                pk.z = *(uint32_t*)&p2; pk.w = *(uint32_t*)&p3;
                *(uint4*)(smem + OFF_X + r * 256 + ((c ^ (r & 7)) * 16)) = pk;
            }
            s += __shfl_xor_sync(0xffffffffu, s, 1);
            s += __shfl_xor_sync(0xffffffffu, s, 2);
            if (sub == 0) ((float*)(smem + OFF_XN))[r] = s;
        }
    }
    __syncthreads();

    // ---- A fragments: warp owns rows mq*32..+31; load once, reuse all chunks
    uint32_t afr[2][8][4];
    {
        int ar = lane & 15, ah = lane >> 4;
#pragma unroll
        for (int mt = 0; mt < 2; mt++) {
            int r = mq * 32 + mt * 16 + ar;
#pragma unroll
            for (int k = 0; k < 8; k++) {
                uint32_t addr = sb + OFF_X + r * 256 + (((2 * k + ah) ^ (r & 7)) * 16);
                LDMATRIX_X4(afr[mt][k], addr);
            }
        }
    }

    const int q  = lane & 3;   // col pair within n8
    const int rp = lane >> 2;  // row within 8
    const uint32_t br_ = lane & 7, bh = lane >> 3;  // B ldmatrix lane mapping
    const int barid = quad + 1;

    const __half2 mtwo = __float2half2_rn(-2.0f);
    const __half2 biginit = __float2half2_rn(60000.0f);
    __half2 rmin2[4] = {biginit, biginit, biginit, biginit};

    // ---- mainloop: quad-private two-stage pipeline over 32 sub-chunks
#pragma unroll 1
    for (int i = 0; i < NSUB; i++) {
        uint32_t buf = (i & 1) ? buf1 : buf0;
        asm volatile("cp.async.wait_group 0;" ::: "memory");
        asm volatile("bar.sync %0, 128;" :: "r"(barid) : "memory");
        if (i + 1 < NSUB)
            issue_sub((i & 1) ? buf0 : buf1, pbase, i + 1, tq);

        const __half2* pnb = (const __half2*)(smem + (buf - sb) + BUFBYTES);
        const uint32_t bl = buf + br_ * 256;
#pragma unroll
        for (int g = 0; g < 4; g++) {   // 4 n8-groups of this sub-chunk
            uint32_t acc[4] = {0u, 0u, 0u, 0u};
#pragma unroll
            for (int kk = 0; kk < 4; kk++) {      // pairs of k16 steps
                uint32_t bfr[4];
                uint32_t addr = bl + g * 2048 + (((4 * kk + bh) ^ br_) * 16);
                LDMATRIX_X4(bfr, addr);
                MMA16816H(acc + 0, afr[0][2 * kk],     bfr[0], bfr[1]);
                MMA16816H(acc + 2, afr[1][2 * kk],     bfr[0], bfr[1]);
                MMA16816H(acc + 0, afr[0][2 * kk + 1], bfr[2], bfr[3]);
                MMA16816H(acc + 2, afr[1][2 * kk + 1], bfr[2], bfr[3]);
            }
            __half2 pp = pnb[g * 4 + q];
            rmin2[0] = __hmin2(rmin2[0], __hfma2(mtwo, *(__half2*)&acc[0], pp));
            rmin2[1] = __hmin2(rmin2[1], __hfma2(mtwo, *(__half2*)&acc[1], pp));
            rmin2[2] = __hmin2(rmin2[2], __hfma2(mtwo, *(__half2*)&acc[2], pp));
            rmin2[3] = __hmin2(rmin2[3], __hfma2(mtwo, *(__half2*)&acc[3], pp));
        }
    }

    // ---- reduce across the quad-of-lanes (4 col-pairs = 8 cols) within each warp
    float rmin[4];
#pragma unroll
    for (int i = 0; i < 4; i++) {
        uint32_t v = *(uint32_t*)&rmin2[i];
        uint32_t v1 = __shfl_xor_sync(0xffffffffu, v, 1);
        __half2 h = __hmin2(*(__half2*)&v, *(__half2*)&v1);
        uint32_t hv = *(uint32_t*)&h;
        uint32_t v2 = __shfl_xor_sync(0xffffffffu, hv, 2);
        h = __hmin2(h, *(__half2*)&v2);
        rmin[i] = fminf(__low2float(h), __high2float(h));
    }
    // rmin[i] = min over this quad's 1024 pts for row mq*32 + i*8 + rp (q==0 lanes)

    // ---- combine the two quads via smem, then epilogue
    float* minbuf = (float*)(smem + OFF_MIN);   // [128]
    if (quad == 1 && q == 0) {
#pragma unroll
        for (int i = 0; i < 4; i++)
            minbuf[mq * 32 + i * 8 + rp] = rmin[i];
    }
    __syncthreads();
    if (quad == 0 && q == 0) {
        const float* xn_s = (const float*)(smem + OFF_XN);
        float brv  = beta_raw[0];
        float beta = fmaxf(brv, 0.f) + log1pf(__expf(-fabsf(brv)));  // softplus
#pragma unroll
        for (int i = 0; i < 4; i++) {
            int rl = mq * 32 + i * 8 + rp;
            float mn  = fminf(rmin[i], minbuf[rl]);
            float md  = fmaxf(xn_s[rl] + mn, 0.f);
            float arg = (md - beta * LOG1000F) / beta;
            out[row0 + rl] = 1.f / (1.f + __expf(-arg));
        }
    }
}

// ---------------------------------------------------------------------------
extern "C" void kernel_launch(void* const* d_in, const int* in_sizes, int n_in,
                              void* d_out, int out_size) {
    const float* x    = (const float*)d_in[0];   // [65536,128]
    const float* pts  = (const float*)d_in[1];   // [2048,128]
    const float* braw = (const float*)d_in[2];   // [1]
    float* out = (float*)d_out;                  // [65536]

    cudaFuncSetAttribute(distnet_main, cudaFuncAttributeMaxDynamicSharedMemorySize,
                         SMEM_BYTES);

    distnet_prep<<<NPTS, DIM>>>(pts);
    distnet_main<<<NROWS / MTILE, 256, SMEM_BYTES>>>(x, braw, out);
}

// round 13
// speedup vs baseline: 1.0679x; 1.0679x over previous
#include <cuda_runtime.h>
#include <cuda_fp16.h>
#include <cstdint>

// ============================================================================
// DistNet: out[n] = sigmoid((max(0, ||x||^2 + min_p(||p||^2 - 2 x.p)) + alpha)/beta)
// R13: quad-sharing (m128, crossbar-amortized) at grid 1024 via point-split:
// 2 CTAs per 128-row tile (1024 pts each), SUBPTS=64, quad-private double
// buffers + named barriers. Cross-CTA combine fused in-kernel: per-half min
// to global, ticket counter, last CTA does sigmoid epilogue + ticket reset.
// ============================================================================

static constexpr int NROWS  = 65536;
static constexpr int DIM    = 128;
static constexpr int NPTS   = 2048;
static constexpr int MTILE  = 128;
static constexpr int NTILES = NROWS / MTILE;  // 512
static constexpr int SUBPTS = 64;             // points per sub-chunk
static constexpr int NSUB   = 512 / SUBPTS;   // 8 sub-chunks per quad (512 pts)

#define LOG1000F 6.9077542789816375f

__device__ __align__(16) __half g_pts[NPTS * DIM];  // fp16 points, K-major
__device__ __align__(16) __half g_pn[NPTS];         // ||p||^2 (fp16)
__device__ float g_hmin[2 * NROWS];                 // per-half row mins
__device__ int   g_tick[NTILES];                    // zero-init tickets

// smem layout (dynamic)
static constexpr int OFF_X     = 0;                    // 128 x 256B = 32768
static constexpr int OFF_B     = 32768;
static constexpr int BUFBYTES  = SUBPTS * 256;         // 16384 per stage buffer
static constexpr int BUFSTRIDE = BUFBYTES + 128;       // + pn (128B)
static constexpr int QUADBYTES = 2 * BUFSTRIDE;        // double buffer
static constexpr int OFF_XN    = OFF_B + 2 * QUADBYTES;   // 98816, 512B
static constexpr int OFF_MIN   = OFF_XN + 512;            // 128 floats
static constexpr int OFF_FLAG  = OFF_MIN + 512;           // 1 int
static constexpr int SMEM_BYTES = OFF_FLAG + 128;         // ~99.8KB -> occ 2

// ---------------------------------------------------------------------------
__device__ __forceinline__ uint32_t smem_u32(const void* p) {
    uint32_t a;
    asm("{ .reg .u64 t; cvta.to.shared.u64 t, %1; cvt.u32.u64 %0, t; }"
        : "=r"(a) : "l"(p));
    return a;
}

__device__ __forceinline__ void cp_async16(uint32_t dst, const void* src) {
    asm volatile("cp.async.cg.shared.global [%0], [%1], 16;"
                 :: "r"(dst), "l"(src) : "memory");
}

#define LDMATRIX_X4(R, ADDR)                                                   \
    asm volatile("ldmatrix.sync.aligned.m8n8.x4.shared.b16 {%0,%1,%2,%3}, [%4];" \
                 : "=r"((R)[0]), "=r"((R)[1]), "=r"((R)[2]), "=r"((R)[3])       \
                 : "r"(ADDR))

#define MMA16816H(C, A, B0, B1)                                                \
    asm volatile("mma.sync.aligned.m16n8k16.row.col.f16.f16.f16.f16 "          \
                 "{%0,%1}, {%2,%3,%4,%5}, {%6,%7}, {%0,%1};"                   \
                 : "+r"((C)[0]), "+r"((C)[1])                                  \
                 : "r"((A)[0]), "r"((A)[1]), "r"((A)[2]), "r"((A)[3]),         \
                   "r"(B0), "r"(B1))

// ---------------------------------------------------------------------------
// Prep: points f32 -> fp16 row-major + ||p||^2 (fp16)
__global__ void distnet_prep(const float* __restrict__ pts) {
    int p = blockIdx.x;
    int t = threadIdx.x;  // 128 = DIM
    float v = pts[p * DIM + t];
    g_pts[p * DIM + t] = __float2half(v);
    float s = v * v;
#pragma unroll
    for (int o = 16; o > 0; o >>= 1) s += __shfl_xor_sync(0xffffffffu, s, o);
    __shared__ float ws[4];
    if ((t & 31) == 0) ws[t >> 5] = s;
    __syncthreads();
    if (t == 0) g_pn[p] = __float2half(ws[0] + ws[1] + ws[2] + ws[3]);
}

// ---------------------------------------------------------------------------
// Quad-scope async copy of one 64-point sub-chunk (16KB B + 128B pn).
// tq in [0,128). base = first point index of this quad's 512-point span.
__device__ __forceinline__ void issue_sub(uint32_t dst, int base, int sub, int tq) {
    const char* src = (const char*)g_pts + ((size_t)base + sub * SUBPTS) * 256;
#pragma unroll
    for (int u = 0; u < 8; u++) {
        int i = tq + u * 128;            // 0..1023 16B units
        int n = i >> 4, c = i & 15;
        cp_async16(dst + n * 256 + ((c ^ (n & 7)) * 16), src + i * 16);
    }
    if (tq < 8)
        cp_async16(dst + BUFBYTES + tq * 16,
                   (const char*)g_pn + ((size_t)base + sub * SUBPTS) * 2 + tq * 16);
    asm volatile("cp.async.commit_group;" ::: "memory");
}

// ---------------------------------------------------------------------------
__global__ void __launch_bounds__(256, 2)
distnet_main(const float* __restrict__ x, const float* __restrict__ beta_raw,
             float* __restrict__ out) {
    extern __shared__ char smem[];
    const uint32_t sb = smem_u32(smem);
    const int tid   = threadIdx.x;
    const int lane  = tid & 31;
    const int wid   = tid >> 5;        // 0..7
    const int mq    = wid & 3;         // m-quarter (32 rows of the 128-row tile)
    const int quad  = wid >> 2;        // 0..1
    const int tq    = tid & 127;       // thread index within quad
    const int tile  = blockIdx.x >> 1;
    const int half  = blockIdx.x & 1;  // which 1024-pt half of the points
    const int row0  = tile * MTILE;
    const int pbase = half * 1024 + quad * 512;

    const uint32_t buf0 = sb + OFF_B + quad * QUADBYTES;
    const uint32_t buf1 = buf0 + BUFSTRIDE;

    issue_sub(buf0, pbase, 0, tq);     // prefetch sub-chunk 0

    // ---- X tile: 128 rows x 256B fp16, 4 threads per row + ||x||^2
    {
        int sub = tid & 3;
#pragma unroll
        for (int pass = 0; pass < 2; pass++) {
            int r = (tid >> 2) + pass * 64;   // 0..127
            const float4* src = (const float4*)(x + (size_t)(row0 + r) * DIM);
            float s = 0.f;
#pragma unroll
            for (int j = 0; j < 4; j++) {
                int c = j * 4 + sub;          // 16B fp16 unit
                float4 v0 = src[c * 2], v1 = src[c * 2 + 1];
                s += v0.x * v0.x + v0.y * v0.y + v0.z * v0.z + v0.w * v0.w;
                s += v1.x * v1.x + v1.y * v1.y + v1.z * v1.z + v1.w * v1.w;
                __half2 p0 = __floats2half2_rn(v0.x, v0.y);
                __half2 p1 = __floats2half2_rn(v0.z, v0.w);
                __half2 p2 = __floats2half2_rn(v1.x, v1.y);
                __half2 p3 = __floats2half2_rn(v1.z, v1.w);
                uint4 pk;
                pk.x = *(uint32_t*)&p0; pk.y = *(uint32_t*)&p1;
                pk.z = *(uint32_t*)&p2; pk.w = *(uint32_t*)&p3;
                *(uint4*)(smem + OFF_X + r * 256 + ((c ^ (r & 7)) * 16)) = pk;
            }
            s += __shfl_xor_sync(0xffffffffu, s, 1);
            s += __shfl_xor_sync(0xffffffffu, s, 2);
            if (sub == 0) ((float*)(smem + OFF_XN))[r] = s;
        }
    }
    __syncthreads();

    // ---- A fragments: warp owns rows mq*32..+31; load once, reuse all chunks
    uint32_t afr[2][8][4];
    {
        int ar = lane & 15, ah = lane >> 4;
#pragma unroll
        for (int mt = 0; mt < 2; mt++) {
            int r = mq * 32 + mt * 16 + ar;
#pragma unroll
            for (int k = 0; k < 8; k++) {
                uint32_t addr = sb + OFF_X + r * 256 + (((2 * k + ah) ^ (r & 7)) * 16);
                LDMATRIX_X4(afr[mt][k], addr);
            }
        }
    }

    const int q  = lane & 3;   // col pair within n8
    const int rp = lane >> 2;  // row within 8
    const uint32_t br_ = lane & 7, bh = lane >> 3;  // B ldmatrix lane mapping
    const int barid = quad + 1;

    const __half2 mtwo = __float2half2_rn(-2.0f);
    const __half2 biginit = __float2half2_rn(60000.0f);
    __half2 rmin2[4] = {biginit, biginit, biginit, biginit};

    // ---- mainloop: quad-private two-stage pipeline over 8 x 64-pt sub-chunks
#pragma unroll 1
    for (int i = 0; i < NSUB; i++) {
        uint32_t buf = (i & 1) ? buf1 : buf0;
        asm volatile("cp.async.wait_group 0;" ::: "memory");
        asm volatile("bar.sync %0, 128;" :: "r"(barid) : "memory");
        if (i + 1 < NSUB)
            issue_sub((i & 1) ? buf0 : buf1, pbase, i + 1, tq);

        const __half2* pnb = (const __half2*)(smem + (buf - sb) + BUFBYTES);
        const uint32_t bl = buf + br_ * 256;
#pragma unroll
        for (int g = 0; g < 8; g++) {   // 8 n8-groups of this 64-pt sub-chunk
            uint32_t acc[4] = {0u, 0u, 0u, 0u};
#pragma unroll
            for (int kk = 0; kk < 4; kk++) {      // pairs of k16 steps
                uint32_t bfr[4];
                uint32_t addr = bl + g * 2048 + (((4 * kk + bh) ^ br_) * 16);
                LDMATRIX_X4(bfr, addr);
                MMA16816H(acc + 0, afr[0][2 * kk],     bfr[0], bfr[1]);
                MMA16816H(acc + 2, afr[1][2 * kk],     bfr[0], bfr[1]);
                MMA16816H(acc + 0, afr[0][2 * kk + 1], bfr[2], bfr[3]);
                MMA16816H(acc + 2, afr[1][2 * kk + 1], bfr[2], bfr[3]);
            }
            __half2 pp = pnb[g * 4 + q];
            rmin2[0] = __hmin2(rmin2[0], __hfma2(mtwo, *(__half2*)&acc[0], pp));
            rmin2[1] = __hmin2(rmin2[1], __hfma2(mtwo, *(__half2*)&acc[1], pp));
            rmin2[2] = __hmin2(rmin2[2], __hfma2(mtwo, *(__half2*)&acc[2], pp));
            rmin2[3] = __hmin2(rmin2[3], __hfma2(mtwo, *(__half2*)&acc[3], pp));
        }
    }

    // ---- reduce across the lane-quad (4 col-pairs = 8 cols) within each warp
    float rmin[4];
#pragma unroll
    for (int i = 0; i < 4; i++) {
        uint32_t v = *(uint32_t*)&rmin2[i];
        uint32_t v1 = __shfl_xor_sync(0xffffffffu, v, 1);
        __half2 h = __hmin2(*(__half2*)&v, *(__half2*)&v1);
        uint32_t hv = *(uint32_t*)&h;
        uint32_t v2 = __shfl_xor_sync(0xffffffffu, hv, 2);
        h = __hmin2(h, *(__half2*)&v2);
        rmin[i] = fminf(__low2float(h), __high2float(h));
    }
    // rmin[i] = min over this quad's 512 pts for row mq*32 + i*8 + rp (q==0)

    // ---- combine the two quads via smem; quad0 writes this CTA's half-min
    float* minbuf = (float*)(smem + OFF_MIN);   // [128]
    if (quad == 1 && q == 0) {
#pragma unroll
        for (int i = 0; i < 4; i++)
            minbuf[mq * 32 + i * 8 + rp] = rmin[i];
    }
    __syncthreads();
    if (quad == 0 && q == 0) {
#pragma unroll
        for (int i = 0; i < 4; i++) {
            int rl = mq * 32 + i * 8 + rp;
            g_hmin[half * NROWS + row0 + rl] = fminf(rmin[i], minbuf[rl]);
        }
    }
    __threadfence();   // all threads: order global min-writes before ticket
    __syncthreads();

    // ---- ticket: last CTA of this tile does the sigmoid epilogue
    int* flag = (int*)(smem + OFF_FLAG);
    if (tid == 0) *flag = atomicAdd(&g_tick[tile], 1);
    __syncthreads();
    if (*flag == 1) {
        __threadfence();   // acquire peer's g_hmin writes
        if (tid < MTILE) {
            const float* xn_s = (const float*)(smem + OFF_XN);
            float brv  = beta_raw[0];
            float beta = fmaxf(brv, 0.f) + log1pf(__expf(-fabsf(brv)));
            float mn = fminf(g_hmin[row0 + tid], g_hmin[NROWS + row0 + tid]);
            float md = fmaxf(xn_s[tid] + mn, 0.f);
            float arg = (md - beta * LOG1000F) / beta;
            out[row0 + tid] = 1.f / (1.f + __expf(-arg));
        }
        if (tid == 0) g_tick[tile] = 0;   // reset for graph replay
    }
}

// ---------------------------------------------------------------------------
extern "C" void kernel_launch(void* const* d_in, const int* in_sizes, int n_in,
                              void* d_out, int out_size) {
    const float* x    = (const float*)d_in[0];   // [65536,128]
    const float* pts  = (const float*)d_in[1];   // [2048,128]
    const float* braw = (const float*)d_in[2];   // [1]
    float* out = (float*)d_out;                  // [65536]

    cudaFuncSetAttribute(distnet_main, cudaFuncAttributeMaxDynamicSharedMemorySize,
                         SMEM_BYTES);

    distnet_prep<<<NPTS, DIM>>>(pts);
    distnet_main<<<NTILES * 2, 256, SMEM_BYTES>>>(x, braw, out);
}